// round 8
// baseline (speedup 1.0000x reference)
#include <cuda_runtime.h>
#include <cstdint>

#define NROWS 131072
#define DIMS  32
#define NC    512
#define NC2   256
#define NBLK  148
#define NTH   256
#define NWARP 8
#define NRT   4096     /* row tiles of 32 */
#define NNT   64       /* n-tiles of 8 centers */

typedef unsigned long long u64;
typedef unsigned int       u32;

// smem layout (bytes):
//   [0, 131072)        B fragments u32[2][64][2][32][4]  (hi/lo splits)
//   [131072, 135168)   tab1 float4[256] {a0,a1,b0,b1}
//   [135168, 139264)   tab2 float4[256] {w00,w01,w10,w11}
//   [139264, 141312)   tab3 float2[256] {w20,w21}
//   [141312, 143360)   tmpA float[512]
//   [143360, 145408)   tmpB float[512]
#define SM_B    0
#define SM_TAB1 131072
#define SM_TAB2 135168
#define SM_TAB3 139264
#define SM_TMPA 141312
#define SM_TMPB 143360
#define SMEM_BYTES 145408

#define FMA2(acc, a, b) \
    asm("fma.rn.f32x2 %0, %1, %2, %0;" : "+l"(acc) : "l"(a), "l"(b))
#define ADD2(d, a, b) \
    asm("add.rn.f32x2 %0, %1, %2;" : "=l"(d) : "l"(a), "l"(b))

__device__ __forceinline__ u64 dup2(float v) {
    u64 r; u32 u = __float_as_uint(v);
    asm("mov.b64 %0, {%1, %1};" : "=l"(r) : "r"(u));
    return r;
}
__device__ __forceinline__ u64 pack2(u32 a, u32 b) {
    u64 r; asm("mov.b64 %0, {%1, %2};" : "=l"(r) : "r"(a), "r"(b));
    return r;
}
__device__ __forceinline__ void unpack2(u64 v, u32& a, u32& b) {
    asm("mov.b64 {%0, %1}, %2;" : "=r"(a), "=r"(b) : "l"(v));
}
__device__ __forceinline__ float tf32_rna(float f) {
    u32 r; asm("cvt.rna.tf32.f32 %0, %1;" : "=r"(r) : "f"(f));
    return __uint_as_float(r);
}

// m16n8k8 tf32 mma, D accumulates in place.
__device__ __forceinline__ void mma8(float* d, const u32* a, u32 b0, u32 b1) {
    asm("mma.sync.aligned.m16n8k8.row.col.f32.tf32.tf32.f32 "
        "{%0,%1,%2,%3}, {%4,%5,%6,%7}, {%8,%9}, {%0,%1,%2,%3};"
        : "+f"(d[0]), "+f"(d[1]), "+f"(d[2]), "+f"(d[3])
        : "r"(a[0]), "r"(a[1]), "r"(a[2]), "r"(a[3]), "r"(b0), "r"(b1));
}

__global__ void __launch_bounds__(NTH, 1)
rbfn_kernel(const float* __restrict__ X,    // [N, 32]
            const float* __restrict__ Cn,   // [512, 32]
            const float* __restrict__ Sg,   // [1, 512]
            const float* __restrict__ Wp,   // [3, 512]
            const float* __restrict__ Bp,   // [3]
            float* __restrict__ O)          // [N, 3]
{
    extern __shared__ unsigned char sm[];
    const int tid  = threadIdx.x;
    const int wid  = tid >> 5, lane = tid & 31;
    const int g    = lane >> 2, tg = lane & 3;
    const float L  = 1.4426950408889634f;   // log2(e)

    // ---- B fill: scaled-center tf32 hi/lo splits in mma B-fragment order ----
    {
        float* tmpA = (float*)(sm + SM_TMPA);
        float* tmpB = (float*)(sm + SM_TMPB);
        u32*   bb   = (u32*)(sm + SM_B);
        for (int c = tid; c < NC; c += NTH) {
            const float4* cr = (const float4*)(Cn + c * DIMS);
            float s  = Sg[c];
            float al = 0.5f * L / (s * s);
            float g2 = 2.0f * al;
            float csq = 0.f;
            const int n = c >> 3, gg = c & 7;
            #pragma unroll
            for (int q = 0; q < 8; ++q) {
                float4 v = cr[q];
                float e[4] = { v.x, v.y, v.z, v.w };
                #pragma unroll
                for (int t = 0; t < 4; ++t) {
                    csq = fmaf(e[t], e[t], csq);
                    float gv = g2 * e[t];
                    float hi = tf32_rna(gv);
                    float lo = tf32_rna(gv - hi);
                    const int d   = q * 4 + t;
                    const int k   = d >> 3, r = d & 7;
                    const int tgg = r & 3,  j = r >> 2;
                    const int k2  = k >> 1, qq = (k & 1) * 2 + j;
                    const int li  = 4 * gg + tgg;
                    bb[(((     n) * 2 + k2) * 32 + li) * 4 + qq] = __float_as_uint(hi);
                    bb[(((64 + n) * 2 + k2) * 32 + li) * 4 + qq] = __float_as_uint(lo);
                }
            }
            tmpA[c] = -al;
            tmpB[c] = -al * csq;
        }
        __syncthreads();
        float4* tab1 = (float4*)(sm + SM_TAB1);
        float4* tab2 = (float4*)(sm + SM_TAB2);
        float2* tab3 = (float2*)(sm + SM_TAB3);
        for (int c2 = tid; c2 < NC2; c2 += NTH) {
            tab1[c2] = make_float4(tmpA[2*c2], tmpA[2*c2+1], tmpB[2*c2], tmpB[2*c2+1]);
            tab2[c2] = make_float4(Wp[0*NC + 2*c2], Wp[0*NC + 2*c2+1],
                                   Wp[1*NC + 2*c2], Wp[1*NC + 2*c2+1]);
            tab3[c2] = make_float2(Wp[2*NC + 2*c2], Wp[2*NC + 2*c2+1]);
        }
        __syncthreads();
    }

    const ulonglong2* tab1u = (const ulonglong2*)(sm + SM_TAB1);
    const ulonglong2* tab2u = (const ulonglong2*)(sm + SM_TAB2);
    const u64*        tab3u = (const u64*)(sm + SM_TAB3);
    const uint4*      bfr   = (const uint4*)(sm + SM_B);
    const float bo0 = Bp[0], bo1 = Bp[1], bo2 = Bp[2];

    // CTA row-tile range; warp strides by NWARP
    const int t0 = (int)(((long long)blockIdx.x * NRT) / NBLK);
    const int t1 = (int)((((long long)blockIdx.x + 1) * NRT) / NBLK);

    for (int rt = t0 + wid; rt < t1; rt += NWARP) {
        const int rb = rt << 5;

        // ---- load 32 x-values (rows g+8i, cols tg+4m), split, xsq ----
        float xv[4][8];
        #pragma unroll
        for (int i = 0; i < 4; ++i) {
            const float* xr = X + (size_t)(rb + g + 8 * i) * DIMS + tg;
            #pragma unroll
            for (int m = 0; m < 8; ++m) xv[i][m] = __ldg(xr + 4 * m);
        }
        u64 xsqd[4];
        #pragma unroll
        for (int i = 0; i < 4; ++i) {
            float p = 0.f;
            #pragma unroll
            for (int m = 0; m < 8; ++m) p = fmaf(xv[i][m], xv[i][m], p);
            p += __shfl_xor_sync(0xffffffffu, p, 1);
            p += __shfl_xor_sync(0xffffffffu, p, 2);
            xsqd[i] = dup2(p);
        }
        // A fragments: [tile*16 + k*4 + reg]
        u32 Ah[32], Al[32];
        #pragma unroll
        for (int t2 = 0; t2 < 2; ++t2) {
            #pragma unroll
            for (int k = 0; k < 4; ++k) {
                const int b = t2 * 16 + k * 4;
                float v0 = xv[2*t2  ][2*k],   v1 = xv[2*t2+1][2*k];
                float v2 = xv[2*t2  ][2*k+1], v3 = xv[2*t2+1][2*k+1];
                float h;
                h = tf32_rna(v0); Ah[b+0] = __float_as_uint(h);
                Al[b+0] = __float_as_uint(tf32_rna(v0 - h));
                h = tf32_rna(v1); Ah[b+1] = __float_as_uint(h);
                Al[b+1] = __float_as_uint(tf32_rna(v1 - h));
                h = tf32_rna(v2); Ah[b+2] = __float_as_uint(h);
                Al[b+2] = __float_as_uint(tf32_rna(v2 - h));
                h = tf32_rna(v3); Ah[b+3] = __float_as_uint(h);
                Al[b+3] = __float_as_uint(tf32_rna(v3 - h));
            }
        }

        u64 op0[4], op1[4], op2[4];
        #pragma unroll
        for (int sl = 0; sl < 4; ++sl) { op0[sl] = 0; op1[sl] = 0; op2[sl] = 0; }

        // preload n-tile 0 B fragments
        uint4 h01 = bfr[0 * 64 + lane];          // ((n)*2+0)*32+lane, n=0
        uint4 h23 = bfr[0 * 64 + 32 + lane];
        uint4 l01 = bfr[128 * 32 + lane];        // ((64+n)*2+0)*32+lane
        uint4 l23 = bfr[128 * 32 + 32 + lane];

        #pragma unroll 1
        for (int n = 0; n < NNT; ++n) {
            // prefetch next n-tile (clamped; extra regs, off critical path)
            const int np = (n + 1) & (NNT - 1);
            uint4 nh01 = bfr[((     np) * 2 + 0) * 32 + lane];
            uint4 nh23 = bfr[((     np) * 2 + 1) * 32 + lane];
            uint4 nl01 = bfr[((64 + np) * 2 + 0) * 32 + lane];
            uint4 nl23 = bfr[((64 + np) * 2 + 1) * 32 + lane];

            // 6 independent accumulator chains: {HH,LH,HL} x {tile0,tile1}
            float hh0[4] = {0,0,0,0}, lh0[4] = {0,0,0,0}, hl0[4] = {0,0,0,0};
            float hh1[4] = {0,0,0,0}, lh1[4] = {0,0,0,0}, hl1[4] = {0,0,0,0};
            // k0
            mma8(hh0, Ah+ 0, h01.x, h01.y); mma8(hh1, Ah+16, h01.x, h01.y);
            mma8(lh0, Al+ 0, h01.x, h01.y); mma8(lh1, Al+16, h01.x, h01.y);
            mma8(hl0, Ah+ 0, l01.x, l01.y); mma8(hl1, Ah+16, l01.x, l01.y);
            // k1
            mma8(hh0, Ah+ 4, h01.z, h01.w); mma8(hh1, Ah+20, h01.z, h01.w);
            mma8(lh0, Al+ 4, h01.z, h01.w); mma8(lh1, Al+20, h01.z, h01.w);
            mma8(hl0, Ah+ 4, l01.z, l01.w); mma8(hl1, Ah+20, l01.z, l01.w);
            // k2
            mma8(hh0, Ah+ 8, h23.x, h23.y); mma8(hh1, Ah+24, h23.x, h23.y);
            mma8(lh0, Al+ 8, h23.x, h23.y); mma8(lh1, Al+24, h23.x, h23.y);
            mma8(hl0, Ah+ 8, l23.x, l23.y); mma8(hl1, Ah+24, l23.x, l23.y);
            // k3
            mma8(hh0, Ah+12, h23.z, h23.w); mma8(hh1, Ah+28, h23.z, h23.w);
            mma8(lh0, Al+12, h23.z, h23.w); mma8(lh1, Al+28, h23.z, h23.w);
            mma8(hl0, Ah+12, l23.z, l23.w); mma8(hl1, Ah+28, l23.z, l23.w);

            // merge split-terms
            float d0[4], d1[4];
            #pragma unroll
            for (int j = 0; j < 4; ++j) {
                d0[j] = hh0[j] + (lh0[j] + hl0[j]);
                d1[j] = hh1[j] + (lh1[j] + hl1[j]);
            }

            // rotate prefetch
            h01 = nh01; h23 = nh23; l01 = nl01; l23 = nl23;

            // ---- epilogue on this n-tile (cols 8n+2tg, 8n+2tg+1) ----
            const int c2 = n * 4 + tg;
            const ulonglong2 ab  = tab1u[c2];
            const ulonglong2 w01 = tab2u[c2];
            const u64        w2v = tab3u[c2];
            #pragma unroll
            for (int sl = 0; sl < 4; ++sl) {
                float p0 = (sl & 1) ? ((sl >> 1) ? d1[2] : d0[2])
                                    : ((sl >> 1) ? d1[0] : d0[0]);
                float p1 = (sl & 1) ? ((sl >> 1) ? d1[3] : d0[3])
                                    : ((sl >> 1) ? d1[1] : d0[1]);
                u64 dp = pack2(__float_as_uint(p0), __float_as_uint(p1));
                u64 tt;
                asm("fma.rn.f32x2 %0, %1, %2, %3;" : "=l"(tt)
                    : "l"(ab.x), "l"(xsqd[sl]), "l"(ab.y));
                ADD2(tt, tt, dp);                     // t/2
                u32 ta, tb; unpack2(tt, ta, tb);
                float e0, e1;
                asm("ex2.approx.ftz.f32 %0, %1;" : "=f"(e0) : "f"(__uint_as_float(ta)));
                asm("ex2.approx.ftz.f32 %0, %1;" : "=f"(e1) : "f"(__uint_as_float(tb)));
                u64 rp = pack2(__float_as_uint(e0), __float_as_uint(e1)), h;
                asm("mul.rn.f32x2 %0, %1, %2;" : "=l"(h) : "l"(rp), "l"(rp));
                FMA2(op0[sl], h, w01.x);
                FMA2(op1[sl], h, w01.y);
                FMA2(op2[sl], h, w2v);
            }
        }

        // ---- reduce over the 4 tg-lanes, store ----
        #pragma unroll
        for (int sl = 0; sl < 4; ++sl) {
            u32 a_, b_;
            float o0, o1, o2;
            unpack2(op0[sl], a_, b_); o0 = __uint_as_float(a_) + __uint_as_float(b_);
            unpack2(op1[sl], a_, b_); o1 = __uint_as_float(a_) + __uint_as_float(b_);
            unpack2(op2[sl], a_, b_); o2 = __uint_as_float(a_) + __uint_as_float(b_);
            o0 += __shfl_xor_sync(0xffffffffu, o0, 1);
            o0 += __shfl_xor_sync(0xffffffffu, o0, 2);
            o1 += __shfl_xor_sync(0xffffffffu, o1, 1);
            o1 += __shfl_xor_sync(0xffffffffu, o1, 2);
            o2 += __shfl_xor_sync(0xffffffffu, o2, 1);
            o2 += __shfl_xor_sync(0xffffffffu, o2, 2);
            if (tg == 0) {
                float* Or = O + (size_t)(rb + g + 8 * sl) * 3;
                Or[0] = o0 + bo0;
                Or[1] = o1 + bo1;
                Or[2] = o2 + bo2;
            }
        }
    }
}

extern "C" void kernel_launch(void* const* d_in, const int* in_sizes, int n_in,
                              void* d_out, int out_size)
{
    const float* X = nullptr; const float* Cn = nullptr; const float* Sg = nullptr;
    const float* Wp = nullptr; const float* Bp = nullptr;
    for (int i = 0; i < n_in; ++i) {
        switch (in_sizes[i]) {
            case NROWS * DIMS: X  = (const float*)d_in[i]; break;
            case NC * DIMS:    Cn = (const float*)d_in[i]; break;
            case NC:           Sg = (const float*)d_in[i]; break;
            case 3 * NC:       Wp = (const float*)d_in[i]; break;
            case 3:            Bp = (const float*)d_in[i]; break;
            default: break;
        }
    }
    if (!X || !Cn || !Sg || !Wp || !Bp) {
        X  = (const float*)d_in[0]; Cn = (const float*)d_in[1];
        Sg = (const float*)d_in[2]; Wp = (const float*)d_in[3];
        Bp = (const float*)d_in[4];
    }

    cudaFuncSetAttribute(rbfn_kernel,
                         cudaFuncAttributeMaxDynamicSharedMemorySize, SMEM_BYTES);
    rbfn_kernel<<<NBLK, NTH, SMEM_BYTES>>>(X, Cn, Sg, Wp, Bp, (float*)d_out);
}

// round 9
// speedup vs baseline: 1.4483x; 1.4483x over previous
#include <cuda_runtime.h>
#include <cuda_fp16.h>
#include <cstdint>

#define NROWS 131072
#define DIMS  32
#define NC    512
#define NC2   256
#define NBLK  148
#define NTH   256
#define NWARP 8
#define NRT   4096     /* row tiles of 32 */
#define NNT   64       /* n-tiles of 8 centers */

typedef unsigned long long u64;
typedef unsigned int       u32;

// smem layout (bytes):
//   [0, 32768)        BH: hi f16 B-fragments  uint4[64][32]
//   [32768, 65536)    BL: lo f16 B-fragments  uint4[64][32]
//   [65536, 69632)    tab1 float4[256] {a0,a1,b0,b1}
//   [69632, 73728)    tab2 float4[256] {w00,w01,w10,w11}
//   [73728, 75776)    tab3 float2[256] {w20,w21}
//   [75776, 77824)    tmpA float[512]
//   [77824, 79872)    tmpB float[512]
#define SM_BH   0
#define SM_BL   32768
#define SM_TAB1 65536
#define SM_TAB2 69632
#define SM_TAB3 73728
#define SM_TMPA 75776
#define SM_TMPB 77824
#define SMEM_BYTES 79872

#define FMA2(acc, a, b) \
    asm("fma.rn.f32x2 %0, %1, %2, %0;" : "+l"(acc) : "l"(a), "l"(b))
#define ADD2(d, a, b) \
    asm("add.rn.f32x2 %0, %1, %2;" : "=l"(d) : "l"(a), "l"(b))

__device__ __forceinline__ u64 dup2(float v) {
    u64 r; u32 u = __float_as_uint(v);
    asm("mov.b64 %0, {%1, %1};" : "=l"(r) : "r"(u));
    return r;
}
__device__ __forceinline__ u64 pack2(u32 a, u32 b) {
    u64 r; asm("mov.b64 %0, {%1, %2};" : "=l"(r) : "r"(a), "r"(b));
    return r;
}
__device__ __forceinline__ void unpack2(u64 v, u32& a, u32& b) {
    asm("mov.b64 {%0, %1}, %2;" : "=r"(a), "=r"(b) : "l"(v));
}

// fp16 hi/lo split of a float2: low 16 bits = .x (lower k index)
__device__ __forceinline__ void split2(float2 v, u32& hi, u32& lo) {
    __half h0 = __float2half_rn(v.x), h1 = __float2half_rn(v.y);
    float  r0 = v.x - __half2float(h0), r1 = v.y - __half2float(h1);
    __half l0 = __float2half_rn(r0), l1 = __float2half_rn(r1);
    hi = (u32)__half_as_ushort(h0) | ((u32)__half_as_ushort(h1) << 16);
    lo = (u32)__half_as_ushort(l0) | ((u32)__half_as_ushort(l1) << 16);
}

// m16n8k16 f16 mma, fp32 accumulate in place.
__device__ __forceinline__ void mma16(float* d, const u32* a, u32 b0, u32 b1) {
    asm("mma.sync.aligned.m16n8k16.row.col.f32.f16.f16.f32 "
        "{%0,%1,%2,%3}, {%4,%5,%6,%7}, {%8,%9}, {%0,%1,%2,%3};"
        : "+f"(d[0]), "+f"(d[1]), "+f"(d[2]), "+f"(d[3])
        : "r"(a[0]), "r"(a[1]), "r"(a[2]), "r"(a[3]), "r"(b0), "r"(b1));
}

__global__ void __launch_bounds__(NTH, 1)
rbfn_kernel(const float* __restrict__ X,    // [N, 32]
            const float* __restrict__ Cn,   // [512, 32]
            const float* __restrict__ Sg,   // [1, 512]
            const float* __restrict__ Wp,   // [3, 512]
            const float* __restrict__ Bp,   // [3]
            float* __restrict__ O)          // [N, 3]
{
    extern __shared__ unsigned char sm[];
    const int tid  = threadIdx.x;
    const int wid  = tid >> 5, lane = tid & 31;
    const int g    = lane >> 2, tg = lane & 3;
    const float L  = 1.4426950408889634f;   // log2(e)

    // ---- B fill: scaled-center f16 hi/lo splits in m16n8k16 B-fragment order ----
    {
        float* tmpA = (float*)(sm + SM_TMPA);
        float* tmpB = (float*)(sm + SM_TMPB);
        unsigned short* bh = (unsigned short*)(sm + SM_BH);
        unsigned short* bl = (unsigned short*)(sm + SM_BL);
        for (int c = tid; c < NC; c += NTH) {
            const float4* cr = (const float4*)(Cn + c * DIMS);
            float s  = Sg[c];
            float al = 0.5f * L / (s * s);
            float g2 = 2.0f * al;
            float csq = 0.f;
            const int n = c >> 3, gg = c & 7;
            #pragma unroll
            for (int q = 0; q < 8; ++q) {
                float4 v = cr[q];
                float e[4] = { v.x, v.y, v.z, v.w };
                #pragma unroll
                for (int t = 0; t < 4; ++t) {
                    csq = fmaf(e[t], e[t], csq);
                    float gv = g2 * e[t];
                    __half hh = __float2half_rn(gv);
                    __half hl = __float2half_rn(gv - __half2float(hh));
                    const int d    = q * 4 + t;
                    const int k2   = d >> 4;          // k-step
                    const int r    = d & 15;
                    const int j    = r >> 3;          // b0 / b1
                    const int rr   = r & 7;
                    const int tgg  = rr >> 1;         // owning tg
                    const int slot = rr & 1;          // half within .b32
                    const int li   = 4 * gg + tgg;    // owning lane (col = g)
                    const int u16i = ((n * 32 + li) * 4 + (k2 * 2 + j)) * 2 + slot;
                    bh[u16i] = __half_as_ushort(hh);
                    bl[u16i] = __half_as_ushort(hl);
                }
            }
            tmpA[c] = -al;
            tmpB[c] = -al * csq;
        }
        __syncthreads();
        float4* tab1 = (float4*)(sm + SM_TAB1);
        float4* tab2 = (float4*)(sm + SM_TAB2);
        float2* tab3 = (float2*)(sm + SM_TAB3);
        for (int c2 = tid; c2 < NC2; c2 += NTH) {
            tab1[c2] = make_float4(tmpA[2*c2], tmpA[2*c2+1], tmpB[2*c2], tmpB[2*c2+1]);
            tab2[c2] = make_float4(Wp[0*NC + 2*c2], Wp[0*NC + 2*c2+1],
                                   Wp[1*NC + 2*c2], Wp[1*NC + 2*c2+1]);
            tab3[c2] = make_float2(Wp[2*NC + 2*c2], Wp[2*NC + 2*c2+1]);
        }
        __syncthreads();
    }

    const ulonglong2* tab1u = (const ulonglong2*)(sm + SM_TAB1);
    const ulonglong2* tab2u = (const ulonglong2*)(sm + SM_TAB2);
    const u64*        tab3u = (const u64*)(sm + SM_TAB3);
    const uint4*      bhf   = (const uint4*)(sm + SM_BH);
    const uint4*      blf   = (const uint4*)(sm + SM_BL);
    const float bo0 = Bp[0], bo1 = Bp[1], bo2 = Bp[2];

    // CTA row-tile range; warp strides by NWARP
    const int t0 = (int)(((long long)blockIdx.x * NRT) / NBLK);
    const int t1 = (int)((((long long)blockIdx.x + 1) * NRT) / NBLK);

    for (int rt = t0 + wid; rt < t1; rt += NWARP) {
        const int rb = rt << 5;

        // ---- load x as float2 pairs: rows rb+g+8i, col pairs (2tg+8j, +1) ----
        float2 xv2[4][4];
        #pragma unroll
        for (int i = 0; i < 4; ++i) {
            const float2* xr = (const float2*)(X + (size_t)(rb + g + 8 * i) * DIMS);
            #pragma unroll
            for (int j = 0; j < 4; ++j) xv2[i][j] = xr[tg + 4 * j];
        }
        u64 xsqd[4];
        #pragma unroll
        for (int i = 0; i < 4; ++i) {
            float p = 0.f;
            #pragma unroll
            for (int j = 0; j < 4; ++j) {
                p = fmaf(xv2[i][j].x, xv2[i][j].x, p);
                p = fmaf(xv2[i][j].y, xv2[i][j].y, p);
            }
            p += __shfl_xor_sync(0xffffffffu, p, 1);
            p += __shfl_xor_sync(0xffffffffu, p, 2);
            xsqd[i] = dup2(p);
        }
        // A fragments: Ah/Al [tile][k-step][4 regs]
        // a0=(row g, k 2tg..+1) a1=(row g+8, same) a2=(row g, k 2tg+8..+9) a3=(row g+8, same)
        u32 Ah[2][2][4], Al[2][2][4];
        #pragma unroll
        for (int t2 = 0; t2 < 2; ++t2)
            #pragma unroll
            for (int k2 = 0; k2 < 2; ++k2) {
                split2(xv2[2*t2    ][2*k2    ], Ah[t2][k2][0], Al[t2][k2][0]);
                split2(xv2[2*t2 + 1][2*k2    ], Ah[t2][k2][1], Al[t2][k2][1]);
                split2(xv2[2*t2    ][2*k2 + 1], Ah[t2][k2][2], Al[t2][k2][2]);
                split2(xv2[2*t2 + 1][2*k2 + 1], Ah[t2][k2][3], Al[t2][k2][3]);
            }

        u64 op0[4], op1[4], op2[4];
        #pragma unroll
        for (int sl = 0; sl < 4; ++sl) { op0[sl] = 0; op1[sl] = 0; op2[sl] = 0; }

        #pragma unroll 1
        for (int n = 0; n < NNT; ++n) {
            uint4 H  = bhf[n * 32 + lane];   // {b0k0, b1k0, b0k1, b1k1} hi
            uint4 Lo = blf[n * 32 + lane];   // same, lo
            float d0[4] = {0,0,0,0}, d1[4] = {0,0,0,0};
            // term xh*gh
            mma16(d0, Ah[0][0], H.x, H.y);  mma16(d1, Ah[1][0], H.x, H.y);
            mma16(d0, Ah[0][1], H.z, H.w);  mma16(d1, Ah[1][1], H.z, H.w);
            // term xl*gh
            mma16(d0, Al[0][0], H.x, H.y);  mma16(d1, Al[1][0], H.x, H.y);
            mma16(d0, Al[0][1], H.z, H.w);  mma16(d1, Al[1][1], H.z, H.w);
            // term xh*gl
            mma16(d0, Ah[0][0], Lo.x, Lo.y); mma16(d1, Ah[1][0], Lo.x, Lo.y);
            mma16(d0, Ah[0][1], Lo.z, Lo.w); mma16(d1, Ah[1][1], Lo.z, Lo.w);

            // ---- epilogue on this n-tile (cols 8n+2tg, 8n+2tg+1) ----
            const int c2 = n * 4 + tg;
            const ulonglong2 ab  = tab1u[c2];
            const ulonglong2 w01 = tab2u[c2];
            const u64        w2v = tab3u[c2];
            #pragma unroll
            for (int sl = 0; sl < 4; ++sl) {
                float p0 = (sl & 1) ? ((sl >> 1) ? d1[2] : d0[2])
                                    : ((sl >> 1) ? d1[0] : d0[0]);
                float p1 = (sl & 1) ? ((sl >> 1) ? d1[3] : d0[3])
                                    : ((sl >> 1) ? d1[1] : d0[1]);
                u64 dp = pack2(__float_as_uint(p0), __float_as_uint(p1));
                u64 tt;
                asm("fma.rn.f32x2 %0, %1, %2, %3;" : "=l"(tt)
                    : "l"(ab.x), "l"(xsqd[sl]), "l"(ab.y));
                ADD2(tt, tt, dp);                     // t/2
                u32 ta, tb; unpack2(tt, ta, tb);
                float e0, e1;
                asm("ex2.approx.ftz.f32 %0, %1;" : "=f"(e0) : "f"(__uint_as_float(ta)));
                asm("ex2.approx.ftz.f32 %0, %1;" : "=f"(e1) : "f"(__uint_as_float(tb)));
                u64 rp = pack2(__float_as_uint(e0), __float_as_uint(e1)), h;
                asm("mul.rn.f32x2 %0, %1, %2;" : "=l"(h) : "l"(rp), "l"(rp));
                FMA2(op0[sl], h, w01.x);
                FMA2(op1[sl], h, w01.y);
                FMA2(op2[sl], h, w2v);
            }
        }

        // ---- reduce over the 4 tg-lanes, store ----
        #pragma unroll
        for (int sl = 0; sl < 4; ++sl) {
            u32 a_, b_;
            float o0, o1, o2;
            unpack2(op0[sl], a_, b_); o0 = __uint_as_float(a_) + __uint_as_float(b_);
            unpack2(op1[sl], a_, b_); o1 = __uint_as_float(a_) + __uint_as_float(b_);
            unpack2(op2[sl], a_, b_); o2 = __uint_as_float(a_) + __uint_as_float(b_);
            o0 += __shfl_xor_sync(0xffffffffu, o0, 1);
            o0 += __shfl_xor_sync(0xffffffffu, o0, 2);
            o1 += __shfl_xor_sync(0xffffffffu, o1, 1);
            o1 += __shfl_xor_sync(0xffffffffu, o1, 2);
            o2 += __shfl_xor_sync(0xffffffffu, o2, 1);
            o2 += __shfl_xor_sync(0xffffffffu, o2, 2);
            if (tg == 0) {
                float* Or = O + (size_t)(rb + g + 8 * sl) * 3;
                Or[0] = o0 + bo0;
                Or[1] = o1 + bo1;
                Or[2] = o2 + bo2;
            }
        }
    }
}

extern "C" void kernel_launch(void* const* d_in, const int* in_sizes, int n_in,
                              void* d_out, int out_size)
{
    const float* X = nullptr; const float* Cn = nullptr; const float* Sg = nullptr;
    const float* Wp = nullptr; const float* Bp = nullptr;
    for (int i = 0; i < n_in; ++i) {
        switch (in_sizes[i]) {
            case NROWS * DIMS: X  = (const float*)d_in[i]; break;
            case NC * DIMS:    Cn = (const float*)d_in[i]; break;
            case NC:           Sg = (const float*)d_in[i]; break;
            case 3 * NC:       Wp = (const float*)d_in[i]; break;
            case 3:            Bp = (const float*)d_in[i]; break;
            default: break;
        }
    }
    if (!X || !Cn || !Sg || !Wp || !Bp) {
        X  = (const float*)d_in[0]; Cn = (const float*)d_in[1];
        Sg = (const float*)d_in[2]; Wp = (const float*)d_in[3];
        Bp = (const float*)d_in[4];
    }

    cudaFuncSetAttribute(rbfn_kernel,
                         cudaFuncAttributeMaxDynamicSharedMemorySize, SMEM_BYTES);
    rbfn_kernel<<<NBLK, NTH, SMEM_BYTES>>>(X, Cn, Sg, Wp, Bp, (float*)d_out);
}

// round 10
// speedup vs baseline: 1.8289x; 1.2627x over previous
#include <cuda_runtime.h>
#include <cuda_fp16.h>
#include <cstdint>

#define NROWS 131072
#define DIMS  32
#define NC    512
#define NC2   256
#define NBLK  148
#define NTH   512
#define NWARP 16
#define NRT   4096     /* row tiles of 32 */
#define NNT   64       /* n-tiles of 8 centers */

typedef unsigned long long u64;
typedef unsigned int       u32;

// smem layout (bytes):
//   [0, 32768)        BH: hi f16 B-fragments  uint4[64][32]
//   [32768, 65536)    BL: lo f16 B-fragments  uint4[64][32]
//   [65536, 69632)    tab1 float4[256] {a0,a1,b0,b1}
//   [69632, 73728)    tab2 float4[256] {w00,w01,w10,w11}
//   [73728, 75776)    tab3 float2[256] {w20,w21}
//   [75776, 77824)    tmpA float[512]
//   [77824, 79872)    tmpB float[512]
#define SM_BH   0
#define SM_BL   32768
#define SM_TAB1 65536
#define SM_TAB2 69632
#define SM_TAB3 73728
#define SM_TMPA 75776
#define SM_TMPB 77824
#define SMEM_BYTES 79872

#define FMA2(acc, a, b) \
    asm("fma.rn.f32x2 %0, %1, %2, %0;" : "+l"(acc) : "l"(a), "l"(b))
#define ADD2(d, a, b) \
    asm("add.rn.f32x2 %0, %1, %2;" : "=l"(d) : "l"(a), "l"(b))

__device__ __forceinline__ u64 dup2(float v) {
    u64 r; u32 u = __float_as_uint(v);
    asm("mov.b64 %0, {%1, %1};" : "=l"(r) : "r"(u));
    return r;
}
__device__ __forceinline__ u64 pack2(u32 a, u32 b) {
    u64 r; asm("mov.b64 %0, {%1, %2};" : "=l"(r) : "r"(a), "r"(b));
    return r;
}
__device__ __forceinline__ void unpack2(u64 v, u32& a, u32& b) {
    asm("mov.b64 {%0, %1}, %2;" : "=r"(a), "=r"(b) : "l"(v));
}

// fp16 hi/lo split of a float2: low 16 bits = .x (lower k index)
__device__ __forceinline__ void split2(float2 v, u32& hi, u32& lo) {
    __half h0 = __float2half_rn(v.x), h1 = __float2half_rn(v.y);
    float  r0 = v.x - __half2float(h0), r1 = v.y - __half2float(h1);
    __half l0 = __float2half_rn(r0), l1 = __float2half_rn(r1);
    hi = (u32)__half_as_ushort(h0) | ((u32)__half_as_ushort(h1) << 16);
    lo = (u32)__half_as_ushort(l0) | ((u32)__half_as_ushort(l1) << 16);
}

// m16n8k16 f16 mma, fp32 accumulate in place.
__device__ __forceinline__ void mma16(float* d, const u32* a, u32 b0, u32 b1) {
    asm("mma.sync.aligned.m16n8k16.row.col.f32.f16.f16.f32 "
        "{%0,%1,%2,%3}, {%4,%5,%6,%7}, {%8,%9}, {%0,%1,%2,%3};"
        : "+f"(d[0]), "+f"(d[1]), "+f"(d[2]), "+f"(d[3])
        : "r"(a[0]), "r"(a[1]), "r"(a[2]), "r"(a[3]), "r"(b0), "r"(b1));
}

__global__ void __launch_bounds__(NTH, 1)
rbfn_kernel(const float* __restrict__ X,    // [N, 32]
            const float* __restrict__ Cn,   // [512, 32]
            const float* __restrict__ Sg,   // [1, 512]
            const float* __restrict__ Wp,   // [3, 512]
            const float* __restrict__ Bp,   // [3]
            float* __restrict__ O)          // [N, 3]
{
    extern __shared__ unsigned char sm[];
    const int tid  = threadIdx.x;
    const int wid  = tid >> 5, lane = tid & 31;
    const int g    = lane >> 2, tg = lane & 3;
    const float L  = 1.4426950408889634f;   // log2(e)

    // ---- B fill: scaled-center f16 hi/lo splits in m16n8k16 B-fragment order ----
    {
        float* tmpA = (float*)(sm + SM_TMPA);
        float* tmpB = (float*)(sm + SM_TMPB);
        unsigned short* bh = (unsigned short*)(sm + SM_BH);
        unsigned short* bl = (unsigned short*)(sm + SM_BL);
        for (int c = tid; c < NC; c += NTH) {
            const float4* cr = (const float4*)(Cn + c * DIMS);
            float s  = Sg[c];
            float al = 0.5f * L / (s * s);
            float g2 = 2.0f * al;
            float csq = 0.f;
            const int n = c >> 3, gg = c & 7;
            #pragma unroll
            for (int q = 0; q < 8; ++q) {
                float4 v = cr[q];
                float e[4] = { v.x, v.y, v.z, v.w };
                #pragma unroll
                for (int t = 0; t < 4; ++t) {
                    csq = fmaf(e[t], e[t], csq);
                    float gv = g2 * e[t];
                    __half hh = __float2half_rn(gv);
                    __half hl = __float2half_rn(gv - __half2float(hh));
                    const int d    = q * 4 + t;
                    const int k2   = d >> 4;          // k-step
                    const int r    = d & 15;
                    const int j    = r >> 3;          // b0 / b1
                    const int rr   = r & 7;
                    const int tgg  = rr >> 1;         // owning tg
                    const int slot = rr & 1;          // half within .b32
                    const int li   = 4 * gg + tgg;    // owning lane (col = g)
                    const int u16i = ((n * 32 + li) * 4 + (k2 * 2 + j)) * 2 + slot;
                    bh[u16i] = __half_as_ushort(hh);
                    bl[u16i] = __half_as_ushort(hl);
                }
            }
            tmpA[c] = -al;
            tmpB[c] = -al * csq;
        }
        __syncthreads();
        float4* tab1 = (float4*)(sm + SM_TAB1);
        float4* tab2 = (float4*)(sm + SM_TAB2);
        float2* tab3 = (float2*)(sm + SM_TAB3);
        for (int c2 = tid; c2 < NC2; c2 += NTH) {
            tab1[c2] = make_float4(tmpA[2*c2], tmpA[2*c2+1], tmpB[2*c2], tmpB[2*c2+1]);
            tab2[c2] = make_float4(Wp[0*NC + 2*c2], Wp[0*NC + 2*c2+1],
                                   Wp[1*NC + 2*c2], Wp[1*NC + 2*c2+1]);
            tab3[c2] = make_float2(Wp[2*NC + 2*c2], Wp[2*NC + 2*c2+1]);
        }
        __syncthreads();
    }

    const ulonglong2* tab1u = (const ulonglong2*)(sm + SM_TAB1);
    const ulonglong2* tab2u = (const ulonglong2*)(sm + SM_TAB2);
    const u64*        tab3u = (const u64*)(sm + SM_TAB3);
    const uint4*      bhf   = (const uint4*)(sm + SM_BH);
    const uint4*      blf   = (const uint4*)(sm + SM_BL);
    const float bo0 = Bp[0], bo1 = Bp[1], bo2 = Bp[2];

    // CTA row-tile range; warp strides by NWARP
    const int t0 = (int)(((long long)blockIdx.x * NRT) / NBLK);
    const int t1 = (int)((((long long)blockIdx.x + 1) * NRT) / NBLK);

    for (int rt = t0 + wid; rt < t1; rt += NWARP) {
        const int rb = rt << 5;

        // ---- load x as float2 pairs: rows rb+g+8i, col pairs (2tg+8j, +1) ----
        float2 xv2[4][4];
        #pragma unroll
        for (int i = 0; i < 4; ++i) {
            const float2* xr = (const float2*)(X + (size_t)(rb + g + 8 * i) * DIMS);
            #pragma unroll
            for (int j = 0; j < 4; ++j) xv2[i][j] = xr[tg + 4 * j];
        }
        u64 xsqd[4];
        #pragma unroll
        for (int i = 0; i < 4; ++i) {
            float p = 0.f;
            #pragma unroll
            for (int j = 0; j < 4; ++j) {
                p = fmaf(xv2[i][j].x, xv2[i][j].x, p);
                p = fmaf(xv2[i][j].y, xv2[i][j].y, p);
            }
            p += __shfl_xor_sync(0xffffffffu, p, 1);
            p += __shfl_xor_sync(0xffffffffu, p, 2);
            xsqd[i] = dup2(p);
        }
        // A fragments: Ah/Al [tile][k-step][4 regs]
        u32 Ah[2][2][4], Al[2][2][4];
        #pragma unroll
        for (int t2 = 0; t2 < 2; ++t2)
            #pragma unroll
            for (int k2 = 0; k2 < 2; ++k2) {
                split2(xv2[2*t2    ][2*k2    ], Ah[t2][k2][0], Al[t2][k2][0]);
                split2(xv2[2*t2 + 1][2*k2    ], Ah[t2][k2][1], Al[t2][k2][1]);
                split2(xv2[2*t2    ][2*k2 + 1], Ah[t2][k2][2], Al[t2][k2][2]);
                split2(xv2[2*t2 + 1][2*k2 + 1], Ah[t2][k2][3], Al[t2][k2][3]);
            }

        u64 op0[4], op1[4], op2[4];
        #pragma unroll
        for (int sl = 0; sl < 4; ++sl) { op0[sl] = 0; op1[sl] = 0; op2[sl] = 0; }

        #pragma unroll 1
        for (int n = 0; n < NNT; ++n) {
            uint4 H  = bhf[n * 32 + lane];   // {b0k0, b1k0, b0k1, b1k1} hi
            uint4 Lo = blf[n * 32 + lane];   // same, lo
            float d0[4] = {0,0,0,0}, d1[4] = {0,0,0,0};
            // term xh*gh
            mma16(d0, Ah[0][0], H.x, H.y);  mma16(d1, Ah[1][0], H.x, H.y);
            mma16(d0, Ah[0][1], H.z, H.w);  mma16(d1, Ah[1][1], H.z, H.w);
            // term xl*gh
            mma16(d0, Al[0][0], H.x, H.y);  mma16(d1, Al[1][0], H.x, H.y);
            mma16(d0, Al[0][1], H.z, H.w);  mma16(d1, Al[1][1], H.z, H.w);
            // term xh*gl
            mma16(d0, Ah[0][0], Lo.x, Lo.y); mma16(d1, Ah[1][0], Lo.x, Lo.y);
            mma16(d0, Ah[0][1], Lo.z, Lo.w); mma16(d1, Ah[1][1], Lo.z, Lo.w);

            // ---- epilogue on this n-tile (cols 8n+2tg, 8n+2tg+1) ----
            const int c2 = n * 4 + tg;
            const ulonglong2 ab  = tab1u[c2];
            const ulonglong2 w01 = tab2u[c2];
            const u64        w2v = tab3u[c2];
            #pragma unroll
            for (int sl = 0; sl < 4; ++sl) {
                float p0 = (sl & 1) ? ((sl >> 1) ? d1[2] : d0[2])
                                    : ((sl >> 1) ? d1[0] : d0[0]);
                float p1 = (sl & 1) ? ((sl >> 1) ? d1[3] : d0[3])
                                    : ((sl >> 1) ? d1[1] : d0[1]);
                u64 dp = pack2(__float_as_uint(p0), __float_as_uint(p1));
                u64 tt;
                asm("fma.rn.f32x2 %0, %1, %2, %3;" : "=l"(tt)
                    : "l"(ab.x), "l"(xsqd[sl]), "l"(ab.y));
                ADD2(tt, tt, dp);                     // t/2
                u32 ta, tb; unpack2(tt, ta, tb);
                float e0, e1;
                asm("ex2.approx.ftz.f32 %0, %1;" : "=f"(e0) : "f"(__uint_as_float(ta)));
                asm("ex2.approx.ftz.f32 %0, %1;" : "=f"(e1) : "f"(__uint_as_float(tb)));
                u64 rp = pack2(__float_as_uint(e0), __float_as_uint(e1)), h;
                asm("mul.rn.f32x2 %0, %1, %2;" : "=l"(h) : "l"(rp), "l"(rp));
                FMA2(op0[sl], h, w01.x);
                FMA2(op1[sl], h, w01.y);
                FMA2(op2[sl], h, w2v);
            }
        }

        // ---- reduce over the 4 tg-lanes, store ----
        #pragma unroll
        for (int sl = 0; sl < 4; ++sl) {
            u32 a_, b_;
            float o0, o1, o2;
            unpack2(op0[sl], a_, b_); o0 = __uint_as_float(a_) + __uint_as_float(b_);
            unpack2(op1[sl], a_, b_); o1 = __uint_as_float(a_) + __uint_as_float(b_);
            unpack2(op2[sl], a_, b_); o2 = __uint_as_float(a_) + __uint_as_float(b_);
            o0 += __shfl_xor_sync(0xffffffffu, o0, 1);
            o0 += __shfl_xor_sync(0xffffffffu, o0, 2);
            o1 += __shfl_xor_sync(0xffffffffu, o1, 1);
            o1 += __shfl_xor_sync(0xffffffffu, o1, 2);
            o2 += __shfl_xor_sync(0xffffffffu, o2, 1);
            o2 += __shfl_xor_sync(0xffffffffu, o2, 2);
            if (tg == 0) {
                float* Or = O + (size_t)(rb + g + 8 * sl) * 3;
                Or[0] = o0 + bo0;
                Or[1] = o1 + bo1;
                Or[2] = o2 + bo2;
            }
        }
    }
}

extern "C" void kernel_launch(void* const* d_in, const int* in_sizes, int n_in,
                              void* d_out, int out_size)
{
    const float* X = nullptr; const float* Cn = nullptr; const float* Sg = nullptr;
    const float* Wp = nullptr; const float* Bp = nullptr;
    for (int i = 0; i < n_in; ++i) {
        switch (in_sizes[i]) {
            case NROWS * DIMS: X  = (const float*)d_in[i]; break;
            case NC * DIMS:    Cn = (const float*)d_in[i]; break;
            case NC:           Sg = (const float*)d_in[i]; break;
            case 3 * NC:       Wp = (const float*)d_in[i]; break;
            case 3:            Bp = (const float*)d_in[i]; break;
            default: break;
        }
    }
    if (!X || !Cn || !Sg || !Wp || !Bp) {
        X  = (const float*)d_in[0]; Cn = (const float*)d_in[1];
        Sg = (const float*)d_in[2]; Wp = (const float*)d_in[3];
        Bp = (const float*)d_in[4];
    }

    cudaFuncSetAttribute(rbfn_kernel,
                         cudaFuncAttributeMaxDynamicSharedMemorySize, SMEM_BYTES);
    rbfn_kernel<<<NBLK, NTH, SMEM_BYTES>>>(X, Cn, Sg, Wp, Bp, (float*)d_out);
}

// round 12
// speedup vs baseline: 1.8814x; 1.0287x over previous
#include <cuda_runtime.h>
#include <cuda_fp16.h>
#include <cstdint>

#define NROWS 131072
#define DIMS  32
#define NC    512
#define NC2   256
#define NBLK  148
#define NTH   512
#define NWARP 16
#define NRT   4096     /* row tiles of 32 */
#define NNT   64       /* n-tiles of 8 centers */

typedef unsigned long long u64;
typedef unsigned int       u32;

// smem layout (bytes):
//   [0, 32768)        BH: hi f16 B-fragments  uint4[64][32]
//   [32768, 65536)    BL: lo f16 B-fragments  uint4[64][32]
//   [65536, 69632)    tab1 float4[256] {a0,a1,b0,b1}
//   [69632, 73728)    tab2 float4[256] {w00,w01,w10,w11}
//   [73728, 75776)    tab3 float2[256] {w20,w21}
//   [75776, 77824)    tmpA float[512]
//   [77824, 79872)    tmpB float[512]
#define SM_BH   0
#define SM_BL   32768
#define SM_TAB1 65536
#define SM_TAB2 69632
#define SM_TAB3 73728
#define SM_TMPA 75776
#define SM_TMPB 77824
#define SMEM_BYTES 79872

#define FMA2(acc, a, b) \
    asm("fma.rn.f32x2 %0, %1, %2, %0;" : "+l"(acc) : "l"(a), "l"(b))
#define ADD2(d, a, b) \
    asm("add.rn.f32x2 %0, %1, %2;" : "=l"(d) : "l"(a), "l"(b))

__device__ __forceinline__ u64 dup2(float v) {
    u64 r; u32 u = __float_as_uint(v);
    asm("mov.b64 %0, {%1, %1};" : "=l"(r) : "r"(u));
    return r;
}
__device__ __forceinline__ u64 pack2(u32 a, u32 b) {
    u64 r; asm("mov.b64 %0, {%1, %2};" : "=l"(r) : "r"(a), "r"(b));
    return r;
}
__device__ __forceinline__ void unpack2(u64 v, u32& a, u32& b) {
    asm("mov.b64 {%0, %1}, %2;" : "=r"(a), "=r"(b) : "l"(v));
}

// fp16 hi/lo split of a float2: low 16 bits = .x (lower k index)
__device__ __forceinline__ void split2(float2 v, u32& hi, u32& lo) {
    __half h0 = __float2half_rn(v.x), h1 = __float2half_rn(v.y);
    float  r0 = v.x - __half2float(h0), r1 = v.y - __half2float(h1);
    __half l0 = __float2half_rn(r0), l1 = __float2half_rn(r1);
    hi = (u32)__half_as_ushort(h0) | ((u32)__half_as_ushort(h1) << 16);
    lo = (u32)__half_as_ushort(l0) | ((u32)__half_as_ushort(l1) << 16);
}

// m16n8k16 f16 mma, fp32 accumulate in place.
__device__ __forceinline__ void mma16(float* d, const u32* a, u32 b0, u32 b1) {
    asm("mma.sync.aligned.m16n8k16.row.col.f32.f16.f16.f32 "
        "{%0,%1,%2,%3}, {%4,%5,%6,%7}, {%8,%9}, {%0,%1,%2,%3};"
        : "+f"(d[0]), "+f"(d[1]), "+f"(d[2]), "+f"(d[3])
        : "r"(a[0]), "r"(a[1]), "r"(a[2]), "r"(a[3]), "r"(b0), "r"(b1));
}

// full 12-mma block for one n-tile into (d0, d1)
__device__ __forceinline__ void mma_block(
    float* d0, float* d1, const u32 Ah[2][2][4], const u32 Al[2][2][4],
    uint4 H, uint4 Lo)
{
    #pragma unroll
    for (int j = 0; j < 4; ++j) { d0[j] = 0.f; d1[j] = 0.f; }
    mma16(d0, Ah[0][0], H.x, H.y);  mma16(d1, Ah[1][0], H.x, H.y);
    mma16(d0, Ah[0][1], H.z, H.w);  mma16(d1, Ah[1][1], H.z, H.w);
    mma16(d0, Al[0][0], H.x, H.y);  mma16(d1, Al[1][0], H.x, H.y);
    mma16(d0, Al[0][1], H.z, H.w);  mma16(d1, Al[1][1], H.z, H.w);
    mma16(d0, Ah[0][0], Lo.x, Lo.y); mma16(d1, Ah[1][0], Lo.x, Lo.y);
    mma16(d0, Ah[0][1], Lo.z, Lo.w); mma16(d1, Ah[1][1], Lo.z, Lo.w);
}

// epilogue for n-tile n from (d0, d1)
__device__ __forceinline__ void epi_tile(
    const float* d0, const float* d1, int n, int tg,
    const ulonglong2* tab1u, const ulonglong2* tab2u, const u64* tab3u,
    const u64* xsqd, u64* op0, u64* op1, u64* op2)
{
    const int c2 = n * 4 + tg;
    const ulonglong2 ab  = tab1u[c2];
    const ulonglong2 w01 = tab2u[c2];
    const u64        w2v = tab3u[c2];
    #pragma unroll
    for (int sl = 0; sl < 4; ++sl) {
        float p0 = (sl & 1) ? ((sl >> 1) ? d1[2] : d0[2])
                            : ((sl >> 1) ? d1[0] : d0[0]);
        float p1 = (sl & 1) ? ((sl >> 1) ? d1[3] : d0[3])
                            : ((sl >> 1) ? d1[1] : d0[1]);
        u64 dp = pack2(__float_as_uint(p0), __float_as_uint(p1));
        u64 tt;
        asm("fma.rn.f32x2 %0, %1, %2, %3;" : "=l"(tt)
            : "l"(ab.x), "l"(xsqd[sl]), "l"(ab.y));
        ADD2(tt, tt, dp);                     // t/2
        u32 ta, tb; unpack2(tt, ta, tb);
        float e0, e1;
        asm("ex2.approx.ftz.f32 %0, %1;" : "=f"(e0) : "f"(__uint_as_float(ta)));
        asm("ex2.approx.ftz.f32 %0, %1;" : "=f"(e1) : "f"(__uint_as_float(tb)));
        u64 rp = pack2(__float_as_uint(e0), __float_as_uint(e1)), h;
        asm("mul.rn.f32x2 %0, %1, %2;" : "=l"(h) : "l"(rp), "l"(rp));
        FMA2(op0[sl], h, w01.x);
        FMA2(op1[sl], h, w01.y);
        FMA2(op2[sl], h, w2v);
    }
}

__global__ void __launch_bounds__(NTH, 1)
rbfn_kernel(const float* __restrict__ X,    // [N, 32]
            const float* __restrict__ Cn,   // [512, 32]
            const float* __restrict__ Sg,   // [1, 512]
            const float* __restrict__ Wp,   // [3, 512]
            const float* __restrict__ Bp,   // [3]
            float* __restrict__ O)          // [N, 3]
{
    extern __shared__ unsigned char sm[];
    const int tid  = threadIdx.x;
    const int wid  = tid >> 5, lane = tid & 31;
    const int g    = lane >> 2, tg = lane & 3;
    const float L  = 1.4426950408889634f;   // log2(e)

    // ---- B fill: scaled-center f16 hi/lo splits in m16n8k16 B-fragment order ----
    {
        float* tmpA = (float*)(sm + SM_TMPA);
        float* tmpB = (float*)(sm + SM_TMPB);
        unsigned short* bh = (unsigned short*)(sm + SM_BH);
        unsigned short* bl = (unsigned short*)(sm + SM_BL);
        for (int c = tid; c < NC; c += NTH) {
            const float4* cr = (const float4*)(Cn + c * DIMS);
            float s  = Sg[c];
            float al = 0.5f * L / (s * s);
            float g2 = 2.0f * al;
            float csq = 0.f;
            const int n = c >> 3, gg = c & 7;
            #pragma unroll
            for (int q = 0; q < 8; ++q) {
                float4 v = cr[q];
                float e[4] = { v.x, v.y, v.z, v.w };
                #pragma unroll
                for (int t = 0; t < 4; ++t) {
                    csq = fmaf(e[t], e[t], csq);
                    float gv = g2 * e[t];
                    __half hh = __float2half_rn(gv);
                    __half hl = __float2half_rn(gv - __half2float(hh));
                    const int d    = q * 4 + t;
                    const int k2   = d >> 4;          // k-step
                    const int r    = d & 15;
                    const int j    = r >> 3;          // b0 / b1
                    const int rr   = r & 7;
                    const int tgg  = rr >> 1;         // owning tg
                    const int slot = rr & 1;          // half within .b32
                    const int li   = 4 * gg + tgg;    // owning lane (col = g)
                    const int u16i = ((n * 32 + li) * 4 + (k2 * 2 + j)) * 2 + slot;
                    bh[u16i] = __half_as_ushort(hh);
                    bl[u16i] = __half_as_ushort(hl);
                }
            }
            tmpA[c] = -al;
            tmpB[c] = -al * csq;
        }
        __syncthreads();
        float4* tab1 = (float4*)(sm + SM_TAB1);
        float4* tab2 = (float4*)(sm + SM_TAB2);
        float2* tab3 = (float2*)(sm + SM_TAB3);
        for (int c2 = tid; c2 < NC2; c2 += NTH) {
            tab1[c2] = make_float4(tmpA[2*c2], tmpA[2*c2+1], tmpB[2*c2], tmpB[2*c2+1]);
            tab2[c2] = make_float4(Wp[0*NC + 2*c2], Wp[0*NC + 2*c2+1],
                                   Wp[1*NC + 2*c2], Wp[1*NC + 2*c2+1]);
            tab3[c2] = make_float2(Wp[2*NC + 2*c2], Wp[2*NC + 2*c2+1]);
        }
        __syncthreads();
    }

    const ulonglong2* tab1u = (const ulonglong2*)(sm + SM_TAB1);
    const ulonglong2* tab2u = (const ulonglong2*)(sm + SM_TAB2);
    const u64*        tab3u = (const u64*)(sm + SM_TAB3);
    const uint4*      bhf   = (const uint4*)(sm + SM_BH);
    const uint4*      blf   = (const uint4*)(sm + SM_BL);
    const float bo0 = Bp[0], bo1 = Bp[1], bo2 = Bp[2];

    // CTA row-tile range; warp strides by NWARP
    const int t0 = (int)(((long long)blockIdx.x * NRT) / NBLK);
    const int t1 = (int)((((long long)blockIdx.x + 1) * NRT) / NBLK);

    for (int rt = t0 + wid; rt < t1; rt += NWARP) {
        const int rb = rt << 5;

        // ---- load x as float2 pairs: rows rb+g+8i, col pairs (2tg+8j, +1) ----
        float2 xv2[4][4];
        #pragma unroll
        for (int i = 0; i < 4; ++i) {
            const float2* xr = (const float2*)(X + (size_t)(rb + g + 8 * i) * DIMS);
            #pragma unroll
            for (int j = 0; j < 4; ++j) xv2[i][j] = xr[tg + 4 * j];
        }
        u64 xsqd[4];
        #pragma unroll
        for (int i = 0; i < 4; ++i) {
            float p = 0.f;
            #pragma unroll
            for (int j = 0; j < 4; ++j) {
                p = fmaf(xv2[i][j].x, xv2[i][j].x, p);
                p = fmaf(xv2[i][j].y, xv2[i][j].y, p);
            }
            p += __shfl_xor_sync(0xffffffffu, p, 1);
            p += __shfl_xor_sync(0xffffffffu, p, 2);
            xsqd[i] = dup2(p);
        }
        // A fragments: Ah/Al [tile][k-step][4 regs]
        u32 Ah[2][2][4], Al[2][2][4];
        #pragma unroll
        for (int t2 = 0; t2 < 2; ++t2)
            #pragma unroll
            for (int k2 = 0; k2 < 2; ++k2) {
                split2(xv2[2*t2    ][2*k2    ], Ah[t2][k2][0], Al[t2][k2][0]);
                split2(xv2[2*t2 + 1][2*k2    ], Ah[t2][k2][1], Al[t2][k2][1]);
                split2(xv2[2*t2    ][2*k2 + 1], Ah[t2][k2][2], Al[t2][k2][2]);
                split2(xv2[2*t2 + 1][2*k2 + 1], Ah[t2][k2][3], Al[t2][k2][3]);
            }

        u64 op0[4], op1[4], op2[4];
        #pragma unroll
        for (int sl = 0; sl < 4; ++sl) { op0[sl] = 0; op1[sl] = 0; op2[sl] = 0; }

        // ---- software-pipelined mainloop: epilogue lags mma by one n-tile ----
        float dA0[4], dA1[4], dB0[4], dB1[4];

        // peel: mma(0)->A, mma(1)->B, epi(0)
        {
            uint4 H  = bhf[lane], Lo = blf[lane];
            mma_block(dA0, dA1, Ah, Al, H, Lo);
            H  = bhf[32 + lane]; Lo = blf[32 + lane];
            mma_block(dB0, dB1, Ah, Al, H, Lo);
            epi_tile(dA0, dA1, 0, tg, tab1u, tab2u, tab3u, xsqd, op0, op1, op2);
        }
        #pragma unroll 1
        for (int np = 1; np < 32; ++np) {
            // mma(2np)->A overlaps epi(2np-1) from B
            uint4 H  = bhf[(2 * np) * 32 + lane];
            uint4 Lo = blf[(2 * np) * 32 + lane];
            mma_block(dA0, dA1, Ah, Al, H, Lo);
            epi_tile(dB0, dB1, 2 * np - 1, tg, tab1u, tab2u, tab3u, xsqd, op0, op1, op2);
            // mma(2np+1)->B overlaps epi(2np) from A
            H  = bhf[(2 * np + 1) * 32 + lane];
            Lo = blf[(2 * np + 1) * 32 + lane];
            mma_block(dB0, dB1, Ah, Al, H, Lo);
            epi_tile(dA0, dA1, 2 * np, tg, tab1u, tab2u, tab3u, xsqd, op0, op1, op2);
        }
        // tail
        epi_tile(dB0, dB1, 63, tg, tab1u, tab2u, tab3u, xsqd, op0, op1, op2);

        // ---- reduce over the 4 tg-lanes, store ----
        #pragma unroll
        for (int sl = 0; sl < 4; ++sl) {
            u32 a_, b_;
            float o0, o1, o2;
            unpack2(op0[sl], a_, b_); o0 = __uint_as_float(a_) + __uint_as_float(b_);
            unpack2(op1[sl], a_, b_); o1 = __uint_as_float(a_) + __uint_as_float(b_);
            unpack2(op2[sl], a_, b_); o2 = __uint_as_float(a_) + __uint_as_float(b_);
            o0 += __shfl_xor_sync(0xffffffffu, o0, 1);
            o0 += __shfl_xor_sync(0xffffffffu, o0, 2);
            o1 += __shfl_xor_sync(0xffffffffu, o1, 1);
            o1 += __shfl_xor_sync(0xffffffffu, o1, 2);
            o2 += __shfl_xor_sync(0xffffffffu, o2, 1);
            o2 += __shfl_xor_sync(0xffffffffu, o2, 2);
            if (tg == 0) {
                float* Or = O + (size_t)(rb + g + 8 * sl) * 3;
                Or[0] = o0 + bo0;
                Or[1] = o1 + bo1;
                Or[2] = o2 + bo2;
            }
        }
    }
}

extern "C" void kernel_launch(void* const* d_in, const int* in_sizes, int n_in,
                              void* d_out, int out_size)
{
    const float* X = nullptr; const float* Cn = nullptr; const float* Sg = nullptr;
    const float* Wp = nullptr; const float* Bp = nullptr;
    for (int i = 0; i < n_in; ++i) {
        switch (in_sizes[i]) {
            case NROWS * DIMS: X  = (const float*)d_in[i]; break;
            case NC * DIMS:    Cn = (const float*)d_in[i]; break;
            case NC:           Sg = (const float*)d_in[i]; break;
            case 3 * NC:       Wp = (const float*)d_in[i]; break;
            case 3:            Bp = (const float*)d_in[i]; break;
            default: break;
        }
    }
    if (!X || !Cn || !Sg || !Wp || !Bp) {
        X  = (const float*)d_in[0]; Cn = (const float*)d_in[1];
        Sg = (const float*)d_in[2]; Wp = (const float*)d_in[3];
        Bp = (const float*)d_in[4];
    }

    cudaFuncSetAttribute(rbfn_kernel,
                         cudaFuncAttributeMaxDynamicSharedMemorySize, SMEM_BYTES);
    rbfn_kernel<<<NBLK, NTH, SMEM_BYTES>>>(X, Cn, Sg, Wp, Bp, (float*)d_out);
}